// round 8
// baseline (speedup 1.0000x reference)
#include <cuda_runtime.h>
#include <cuda_bf16.h>
#include <stdint.h>

// GCN 2-layer, atomic-scatter formulation:
//   g   = (x @ W) * dinv[row]           (dinv = rsqrt(indeg+1))
//   acc[d] = g[d] + sum_{e:dst=d} g[src_e]      (red.global.add.v4)
//   y   = dinv[d] * acc[d] + b

#define NMAX 100096
#define F_IN 128
#define H1 32
#define H2 16

__device__ float g_cnt[NMAX];         // degree+1 (float)
__device__ float g_dinv[NMAX];
__device__ float g_g1[NMAX * H1];
__device__ float g_acc1[NMAX * H1];
__device__ float g_g2[NMAX * H2];

// packed f32x2 FMA (Blackwell sm_100+): d = a*b + c on both 32-bit halves
__device__ __forceinline__ unsigned long long fma2(unsigned long long a,
                                                   unsigned long long b,
                                                   unsigned long long c) {
    unsigned long long d;
    asm("fma.rn.f32x2 %0, %1, %2, %3;" : "=l"(d) : "l"(a), "l"(b), "l"(c));
    return d;
}
__device__ __forceinline__ unsigned long long pack2(float lo, float hi) {
    unsigned long long d;
    asm("mov.b64 %0, {%1, %2};" : "=l"(d) : "f"(lo), "f"(hi));
    return d;
}
__device__ __forceinline__ float2 unpack2(unsigned long long v) {
    float lo, hi;
    asm("mov.b64 {%0, %1}, %2;" : "=f"(lo), "=f"(hi) : "l"(v));
    return make_float2(lo, hi);
}

// ---------------------------------------------------------------- degree ----
__global__ void k_init_deg(int n) {
    int i = blockIdx.x * blockDim.x + threadIdx.x;
    if (i < n) g_cnt[i] = 1.0f;  // self loop
}

__global__ void k_count_deg(const int* __restrict__ dst, int E) {
    int e = blockIdx.x * blockDim.x + threadIdx.x;
    if (e < E) atomicAdd(&g_cnt[dst[e]], 1.0f);  // no-return -> RED
}

// ------------------------------------------------------------- layer 1 ------
// Register-tiled GEMM with packed f32x2 FMAs. Thread = 4 rows x 4 cols; the
// K dimension is processed in (k, k+1) pairs: x chunks reinterpret natively
// as f32x2, W1 staged in smem as k-pair-interleaved 64-bit words. Each
// accumulator holds (even-k partial, odd-k partial); halves summed at end.
__global__ void __launch_bounds__(256) k_gemm1(const float* __restrict__ x,
                                               const float* __restrict__ W1, int n) {
    __shared__ unsigned long long Wp[(F_IN / 2) * H1];   // 16 KB: [k2][c]
    int tid = threadIdx.x;
    for (int i = tid; i < (F_IN / 2) * H1; i += 256) {
        int k2 = i >> 5, c = i & 31;
        Wp[i] = pack2(W1[(2 * k2) * H1 + c], W1[(2 * k2 + 1) * H1 + c]);
    }
    __syncthreads();

    int lane = tid & 31, warp = tid >> 5;
    int c0 = (lane & 7) * 4;
    int rg = lane >> 3;
    int rowbase = blockIdx.x * 128 + warp * 16 + rg * 4;

    const float* xp[4];
#pragma unroll
    for (int r = 0; r < 4; r++) {
        int rc = rowbase + r;
        rc = rc < n ? rc : n - 1;  // clamp (tail only)
        xp[r] = x + (size_t)rc * F_IN;
    }

    unsigned long long acc[4][4] = {};   // f32x2 partial pairs
    ulonglong2 xv[4];                    // (x[k],x[k+1]) , (x[k+2],x[k+3])
#pragma unroll
    for (int r = 0; r < 4; r++) xv[r] = __ldg((const ulonglong2*)xp[r]);

#pragma unroll
    for (int k4 = 0; k4 < F_IN; k4 += 4) {
        ulonglong2 cur[4];
#pragma unroll
        for (int r = 0; r < 4; r++) cur[r] = xv[r];
        if (k4 + 4 < F_IN) {
#pragma unroll
            for (int r = 0; r < 4; r++)
                xv[r] = __ldg((const ulonglong2*)(xp[r] + k4 + 4));
        }
        int k2 = k4 >> 1;
        // cols c0..c0+3, k-pair A (k4,k4+1) and B (k4+2,k4+3)
        ulonglong2 wA0 = *(const ulonglong2*)&Wp[k2 * H1 + c0];
        ulonglong2 wA1 = *(const ulonglong2*)&Wp[k2 * H1 + c0 + 2];
        ulonglong2 wB0 = *(const ulonglong2*)&Wp[(k2 + 1) * H1 + c0];
        ulonglong2 wB1 = *(const ulonglong2*)&Wp[(k2 + 1) * H1 + c0 + 2];
#pragma unroll
        for (int r = 0; r < 4; r++) {
            acc[r][0] = fma2(cur[r].x, wA0.x, acc[r][0]);
            acc[r][1] = fma2(cur[r].x, wA0.y, acc[r][1]);
            acc[r][2] = fma2(cur[r].x, wA1.x, acc[r][2]);
            acc[r][3] = fma2(cur[r].x, wA1.y, acc[r][3]);
            acc[r][0] = fma2(cur[r].y, wB0.x, acc[r][0]);
            acc[r][1] = fma2(cur[r].y, wB0.y, acc[r][1]);
            acc[r][2] = fma2(cur[r].y, wB1.x, acc[r][2]);
            acc[r][3] = fma2(cur[r].y, wB1.y, acc[r][3]);
        }
    }

#pragma unroll
    for (int r = 0; r < 4; r++) {
        int row = rowbase + r;
        if (row < n) {
            float di = rsqrtf(g_cnt[row]);
            if (c0 == 0) g_dinv[row] = di;  // one writer per row (colgroup 0)
            float2 p0 = unpack2(acc[r][0]);
            float2 p1 = unpack2(acc[r][1]);
            float2 p2 = unpack2(acc[r][2]);
            float2 p3 = unpack2(acc[r][3]);
            float4 v = make_float4((p0.x + p0.y) * di, (p1.x + p1.y) * di,
                                   (p2.x + p2.y) * di, (p3.x + p3.y) * di);
            *(float4*)&g_g1[row * H1 + c0]   = v;
            *(float4*)&g_acc1[row * H1 + c0] = v;
        }
    }
}

// per-edge scatter: acc1[dst] += g1[src]  (32 floats = 8 x red.v4)
__global__ void k_scatter1(const int* __restrict__ src, const int* __restrict__ dst, int E) {
    long long tid = (long long)blockIdx.x * blockDim.x + threadIdx.x;
    if (tid >= (long long)E * 8) return;
    int e = (int)(tid >> 3), c = (int)(tid & 7);
    int s = __ldg(&src[e]);
    int d = __ldg(&dst[e]);
    float4 v = ((const float4*)(g_g1 + s * H1))[c];
    float* p = g_acc1 + d * H1 + c * 4;
    asm volatile("red.global.add.v4.f32 [%0], {%1,%2,%3,%4};"
                 :: "l"(p), "f"(v.x), "f"(v.y), "f"(v.z), "f"(v.w) : "memory");
}

// epilogue layer1 + GEMM2 fused (warp shuffles), writes g2 and out self-loop.
__global__ void k_finish1_gemm2(const float* __restrict__ W2, const float* __restrict__ b1,
                                float* __restrict__ out, int n) {
    __shared__ float W2s[H1 * H2];  // 2 KB
    __shared__ float b1s[H1];
    int tid = threadIdx.x;  // 256
    for (int i = tid; i < H1 * H2; i += 256) W2s[i] = W2[i];
    if (tid < H1) b1s[tid] = b1[tid];
    __syncthreads();

    int warp = tid >> 5, lane = tid & 31;
    int row = blockIdx.x * 8 + warp;
    if (row >= n) return;

    float di = g_dinv[row];
    float h = fmaxf(fmaf(di, g_acc1[row * H1 + lane], b1s[lane]), 0.0f);

    float acc = 0.0f;
    int j = lane & 15;
#pragma unroll
    for (int k = 0; k < H1; k++) {
        float v = __shfl_sync(0xffffffffu, h, k);
        acc = fmaf(v, W2s[k * H2 + j], acc);
    }
    if (lane < H2) {
        float g = acc * di;
        g_g2[row * H2 + lane] = g;
        out[row * H2 + lane]  = g;
    }
}

// per-edge scatter layer 2: out[dst] += g2[src]  (16 floats = 4 x red.v4)
__global__ void k_scatter2(const int* __restrict__ src, const int* __restrict__ dst,
                           float* __restrict__ out, int E) {
    long long tid = (long long)blockIdx.x * blockDim.x + threadIdx.x;
    if (tid >= (long long)E * 4) return;
    int e = (int)(tid >> 2), c = (int)(tid & 3);
    int s = __ldg(&src[e]);
    int d = __ldg(&dst[e]);
    float4 v = ((const float4*)(g_g2 + s * H2))[c];
    float* p = out + d * H2 + c * 4;
    asm volatile("red.global.add.v4.f32 [%0], {%1,%2,%3,%4};"
                 :: "l"(p), "f"(v.x), "f"(v.y), "f"(v.z), "f"(v.w) : "memory");
}

__global__ void k_finish2(float* __restrict__ out, const float* __restrict__ b2, int total) {
    int i = blockIdx.x * blockDim.x + threadIdx.x;
    if (i < total) {
        out[i] = fmaf(g_dinv[i >> 4], out[i], __ldg(&b2[i & 15]));
    }
}

// ------------------------------------------------------------------ host ----
extern "C" void kernel_launch(void* const* d_in, const int* in_sizes, int n_in,
                              void* d_out, int out_size) {
    const float* x  = (const float*)d_in[0];
    const int*   ei = (const int*)d_in[1];
    const float* W1 = (const float*)d_in[2];
    const float* b1 = (const float*)d_in[3];
    const float* W2 = (const float*)d_in[4];
    const float* b2 = (const float*)d_in[5];
    float* out = (float*)d_out;

    int n = in_sizes[0] / F_IN;   // 100000
    int E = in_sizes[1] / 2;      // 3200000
    const int* src = ei;
    const int* dst = ei + E;

    k_init_deg<<<(n + 255) / 256, 256>>>(n);
    k_count_deg<<<(E + 255) / 256, 256>>>(dst, E);

    k_gemm1<<<(n + 127) / 128, 256>>>(x, W1, n);
    k_scatter1<<<(int)(((long long)E * 8 + 255) / 256), 256>>>(src, dst, E);
    k_finish1_gemm2<<<(n + 7) / 8, 256>>>(W2, b1, out, n);
    k_scatter2<<<(int)(((long long)E * 4 + 255) / 256), 256>>>(src, dst, out, E);
    k_finish2<<<(n * H2 + 255) / 256, 256>>>(out, b2, n * H2);
}

// round 10
// speedup vs baseline: 1.0497x; 1.0497x over previous
#include <cuda_runtime.h>
#include <cuda_bf16.h>
#include <stdint.h>

// GCN 2-layer, atomic-scatter formulation:
//   g   = (x @ W) * dinv[row]           (dinv = rsqrt(indeg+1))
//   acc[d] = g[d] + sum_{e:dst=d} g[src_e]      (red.global.add.v4)
//   y   = dinv[d] * acc[d] + b

#define NMAX 100096
#define F_IN 128
#define H1 32
#define H2 16

__device__ float g_cnt[NMAX];         // edge in-degree (float), +1 folded later
__device__ float g_dinv[NMAX];
__device__ float g_g1[NMAX * H1];
__device__ float g_acc1[NMAX * H1];
__device__ float g_g2[NMAX * H2];

// ---------------------------------------------------------------- degree ----
__global__ void k_zero_deg(int n) {
    int i = blockIdx.x * blockDim.x + threadIdx.x;
    if (i < n) g_cnt[i] = 0.0f;
}

__global__ void k_count_deg(const int* __restrict__ dst, int E) {
    int e = blockIdx.x * blockDim.x + threadIdx.x;
    if (e < E) atomicAdd(&g_cnt[dst[e]], 1.0f);  // no-return -> RED
}

// ------------------------------------------------------------- layer 1 ------
// Register-tiled GEMM: thread = 4 rows x 4 cols; warp = 4 rowgroups x 8
// colgroups -> 16 rows; block (8 warps) -> 128 rows. x prefetched one k4
// ahead. Also computes and stores dinv (self-loop +1 folded here), and
// initializes acc1 = g1.
__global__ void __launch_bounds__(256) k_gemm1(const float* __restrict__ x,
                                               const float* __restrict__ W1, int n) {
    __shared__ float Ws[F_IN * H1];   // 16 KB
    int tid = threadIdx.x;
    for (int i = tid; i < F_IN * H1; i += 256) Ws[i] = W1[i];
    __syncthreads();

    int lane = tid & 31, warp = tid >> 5;
    int c0 = (lane & 7) * 4;
    int rg = lane >> 3;
    int rowbase = blockIdx.x * 128 + warp * 16 + rg * 4;

    const float* xp[4];
#pragma unroll
    for (int r = 0; r < 4; r++) {
        int rc = rowbase + r;
        rc = rc < n ? rc : n - 1;  // clamp (tail only)
        xp[r] = x + (size_t)rc * F_IN;
    }

    float acc[4][4] = {};
    float4 xv[4];
#pragma unroll
    for (int r = 0; r < 4; r++) xv[r] = __ldg((const float4*)xp[r]);

#pragma unroll
    for (int k4 = 0; k4 < F_IN; k4 += 4) {
        float4 cur[4];
#pragma unroll
        for (int r = 0; r < 4; r++) cur[r] = xv[r];
        if (k4 + 4 < F_IN) {
#pragma unroll
            for (int r = 0; r < 4; r++) xv[r] = __ldg((const float4*)(xp[r] + k4 + 4));
        }
        float4 w0 = *(const float4*)&Ws[(k4 + 0) * H1 + c0];
        float4 w1 = *(const float4*)&Ws[(k4 + 1) * H1 + c0];
        float4 w2 = *(const float4*)&Ws[(k4 + 2) * H1 + c0];
        float4 w3 = *(const float4*)&Ws[(k4 + 3) * H1 + c0];
#pragma unroll
        for (int r = 0; r < 4; r++) {
            acc[r][0] = fmaf(cur[r].x, w0.x, acc[r][0]);
            acc[r][1] = fmaf(cur[r].x, w0.y, acc[r][1]);
            acc[r][2] = fmaf(cur[r].x, w0.z, acc[r][2]);
            acc[r][3] = fmaf(cur[r].x, w0.w, acc[r][3]);
            acc[r][0] = fmaf(cur[r].y, w1.x, acc[r][0]);
            acc[r][1] = fmaf(cur[r].y, w1.y, acc[r][1]);
            acc[r][2] = fmaf(cur[r].y, w1.z, acc[r][2]);
            acc[r][3] = fmaf(cur[r].y, w1.w, acc[r][3]);
            acc[r][0] = fmaf(cur[r].z, w2.x, acc[r][0]);
            acc[r][1] = fmaf(cur[r].z, w2.y, acc[r][1]);
            acc[r][2] = fmaf(cur[r].z, w2.z, acc[r][2]);
            acc[r][3] = fmaf(cur[r].z, w2.w, acc[r][3]);
            acc[r][0] = fmaf(cur[r].w, w3.x, acc[r][0]);
            acc[r][1] = fmaf(cur[r].w, w3.y, acc[r][1]);
            acc[r][2] = fmaf(cur[r].w, w3.z, acc[r][2]);
            acc[r][3] = fmaf(cur[r].w, w3.w, acc[r][3]);
        }
    }

#pragma unroll
    for (int r = 0; r < 4; r++) {
        int row = rowbase + r;
        if (row < n) {
            float di = rsqrtf(g_cnt[row] + 1.0f);   // +1 = self loop
            if (c0 == 0) g_dinv[row] = di;  // one writer per row (colgroup 0)
            float4 v = make_float4(acc[r][0] * di, acc[r][1] * di,
                                   acc[r][2] * di, acc[r][3] * di);
            *(float4*)&g_g1[row * H1 + c0]   = v;
            *(float4*)&g_acc1[row * H1 + c0] = v;
        }
    }
}

// per-edge scatter: acc1[dst] += g1[src]  (32 floats = 8 x red.v4)
__global__ void k_scatter1(const int* __restrict__ src, const int* __restrict__ dst, int E) {
    long long tid = (long long)blockIdx.x * blockDim.x + threadIdx.x;
    if (tid >= (long long)E * 8) return;
    int e = (int)(tid >> 3), c = (int)(tid & 7);
    int s = __ldg(&src[e]);
    int d = __ldg(&dst[e]);
    float4 v = ((const float4*)(g_g1 + s * H1))[c];
    float* p = g_acc1 + d * H1 + c * 4;
    asm volatile("red.global.add.v4.f32 [%0], {%1,%2,%3,%4};"
                 :: "l"(p), "f"(v.x), "f"(v.y), "f"(v.z), "f"(v.w) : "memory");
}

// epilogue layer1 + GEMM2 fused (warp shuffles), writes g2 and out self-loop.
__global__ void k_finish1_gemm2(const float* __restrict__ W2, const float* __restrict__ b1,
                                float* __restrict__ out, int n) {
    __shared__ float W2s[H1 * H2];  // 2 KB
    __shared__ float b1s[H1];
    int tid = threadIdx.x;  // 256
    for (int i = tid; i < H1 * H2; i += 256) W2s[i] = W2[i];
    if (tid < H1) b1s[tid] = b1[tid];
    __syncthreads();

    int warp = tid >> 5, lane = tid & 31;
    int row = blockIdx.x * 8 + warp;
    if (row >= n) return;

    float di = g_dinv[row];
    float h = fmaxf(fmaf(di, g_acc1[row * H1 + lane], b1s[lane]), 0.0f);

    float acc = 0.0f;
    int j = lane & 15;
#pragma unroll
    for (int k = 0; k < H1; k++) {
        float v = __shfl_sync(0xffffffffu, h, k);
        acc = fmaf(v, W2s[k * H2 + j], acc);
    }
    if (lane < H2) {
        float g = acc * di;
        g_g2[row * H2 + lane] = g;
        out[row * H2 + lane]  = g;
    }
}

// per-edge scatter layer 2: out[dst] += g2[src]  (16 floats = 4 x red.v4)
__global__ void k_scatter2(const int* __restrict__ src, const int* __restrict__ dst,
                           float* __restrict__ out, int E) {
    long long tid = (long long)blockIdx.x * blockDim.x + threadIdx.x;
    if (tid >= (long long)E * 4) return;
    int e = (int)(tid >> 2), c = (int)(tid & 3);
    int s = __ldg(&src[e]);
    int d = __ldg(&dst[e]);
    float4 v = ((const float4*)(g_g2 + s * H2))[c];
    float* p = out + d * H2 + c * 4;
    asm volatile("red.global.add.v4.f32 [%0], {%1,%2,%3,%4};"
                 :: "l"(p), "f"(v.x), "f"(v.y), "f"(v.z), "f"(v.w) : "memory");
}

// vectorized: thread handles 4 consecutive outputs (quarter-row of H2=16)
__global__ void k_finish2(float* __restrict__ out, const float* __restrict__ b2, int nquads) {
    int i = blockIdx.x * blockDim.x + threadIdx.x;
    if (i < nquads) {
        int row = i >> 2;            // 4 quads per row of 16
        int q = (i & 3) * 4;
        float di = g_dinv[row];
        float4 b = *(const float4*)&b2[q];
        float4 v = *(float4*)&out[row * H2 + q];
        v.x = fmaf(di, v.x, b.x);
        v.y = fmaf(di, v.y, b.y);
        v.z = fmaf(di, v.z, b.z);
        v.w = fmaf(di, v.w, b.w);
        *(float4*)&out[row * H2 + q] = v;
    }
}

// ------------------------------------------------------------------ host ----
extern "C" void kernel_launch(void* const* d_in, const int* in_sizes, int n_in,
                              void* d_out, int out_size) {
    const float* x  = (const float*)d_in[0];
    const int*   ei = (const int*)d_in[1];
    const float* W1 = (const float*)d_in[2];
    const float* b1 = (const float*)d_in[3];
    const float* W2 = (const float*)d_in[4];
    const float* b2 = (const float*)d_in[5];
    float* out = (float*)d_out;

    int n = in_sizes[0] / F_IN;   // 100000
    int E = in_sizes[1] / 2;      // 3200000
    const int* src = ei;
    const int* dst = ei + E;

    k_zero_deg<<<(n + 255) / 256, 256>>>(n);
    k_count_deg<<<(E + 255) / 256, 256>>>(dst, E);
    k_gemm1<<<(n + 127) / 128, 256>>>(x, W1, n);
    k_scatter1<<<(int)(((long long)E * 8 + 255) / 256), 256>>>(src, dst, E);
    k_finish1_gemm2<<<(n + 7) / 8, 256>>>(W2, b1, out, n);
    k_scatter2<<<(int)(((long long)E * 4 + 255) / 256), 256>>>(src, dst, out, E);
    k_finish2<<<(n * 4 + 255) / 256, 256>>>(out, b2, n * 4);
}